// round 11
// baseline (speedup 1.0000x reference)
#include <cuda_runtime.h>
#include <stdint.h>

// ProbabilisticPrediction fused kernel, R11 = R6 (best: 14.8us) + three
// issue-count reductions: funnel-shift threefry rotations, float4 logits
// load in phase 1, and a layer-3 rebalance (8 weight LDGs reused over 4 rows
// instead of 32 LDGs). 8 rows/block, 1024 threads, grid 128.
// Gumbel-argmax (JAX threefry partitionable) selects one mixture component
// per (b,q); the 3-layer MLP is evaluated only at those 1024 points.

#define B_   4
#define QL_  256
#define CL_  512
#define DIM_ 128
#define YD_  16
#define R_   8

#ifdef __CUDA_ARCH__
#define ROTL32(x, d) __funnelshift_l((x), (x), (d))
#else
#define ROTL32(x, d) (((x) << (d)) | ((x) >> (32 - (d))))
#endif

// ---------------------------------------------------------------- threefry2x32
__host__ __device__ inline void tf2x32(uint32_t k0, uint32_t k1,
                                       uint32_t c0, uint32_t c1,
                                       uint32_t& o0, uint32_t& o1) {
    uint32_t k2 = k0 ^ k1 ^ 0x1BD11BDAu;
    uint32_t x0 = c0 + k0, x1 = c1 + k1;
#define TFR(d) do { x0 += x1; x1 = ROTL32(x1, d); x1 ^= x0; } while (0)
    TFR(13); TFR(15); TFR(26); TFR(6);   x0 += k1; x1 += k2 + 1u;
    TFR(17); TFR(29); TFR(16); TFR(24);  x0 += k2; x1 += k0 + 2u;
    TFR(13); TFR(15); TFR(26); TFR(6);   x0 += k0; x1 += k1 + 3u;
    TFR(17); TFR(29); TFR(16); TFR(24);  x0 += k1; x1 += k2 + 4u;
    TFR(13); TFR(15); TFR(26); TFR(6);   x0 += k2; x1 += k0 + 5u;
#undef TFR
    o0 = x0; o1 = x1;
}

__device__ inline uint32_t jax_bits(uint32_t k0, uint32_t k1, uint32_t j) {
    uint32_t o0, o1;
    tf2x32(k0, k1, 0u, j, o0, o1);   // partitionable: 64-bit iota (0, j)
    return o0 ^ o1;
}

__device__ inline float bits_to_unit(uint32_t b) {      // [0, 1)
    return __uint_as_float((b >> 9) | 0x3f800000u) - 1.0f;
}

// XLA ErfInv32 (Giles) -- matches jax.random.normal exactly.
__device__ inline float erfinv_xla(float x) {
    float w = -log1pf(-x * x);
    float p;
    if (w < 5.0f) {
        w -= 2.5f;
        p =            2.81022636e-08f;
        p = fmaf(p, w, 3.43273939e-07f);
        p = fmaf(p, w, -3.5233877e-06f);
        p = fmaf(p, w, -4.39150654e-06f);
        p = fmaf(p, w, 0.00021858087f);
        p = fmaf(p, w, -0.00125372503f);
        p = fmaf(p, w, -0.00417768164f);
        p = fmaf(p, w, 0.246640727f);
        p = fmaf(p, w, 1.50140941f);
    } else {
        w = sqrtf(w) - 3.0f;
        p =            -0.000200214257f;
        p = fmaf(p, w, 0.000100950558f);
        p = fmaf(p, w, 0.00134934322f);
        p = fmaf(p, w, -0.00367342844f);
        p = fmaf(p, w, 0.00573950773f);
        p = fmaf(p, w, -0.0076224613f);
        p = fmaf(p, w, 0.00943887047f);
        p = fmaf(p, w, 1.00167406f);
        p = fmaf(p, w, 2.83297682f);
    }
    return p * x;
}

// ---------------------------------------------------------------------- kernel
__global__ __launch_bounds__(1024, 1)
void pp_fused_kernel(const float* __restrict__ q,
                     const float* __restrict__ f_embed,
                     const float* __restrict__ att_logits,
                     const float* __restrict__ W1q,
                     const float* __restrict__ W1f,
                     const float* __restrict__ b1,
                     const float* __restrict__ W2,
                     const float* __restrict__ b2,
                     const float* __restrict__ Wout,
                     const float* __restrict__ bout,
                     float* __restrict__ out,
                     uint32_t kc0, uint32_t kc1,
                     uint32_t ke0, uint32_t ke1)
{
    const int t   = threadIdx.x;         // 0..1023
    const int w   = t >> 5;              // warp 0..31
    const int ln  = t & 31;
    const int bq0 = blockIdx.x * R_;
    const int b   = bq0 >> 8;            // all R_ rows share b (8 | 256)

    __shared__ float sQ[R_ * DIM_];      // q rows; later h2
    __shared__ float sF[R_ * DIM_];      // selected f rows
    __shared__ float sH[R_ * DIM_];      // h1
    __shared__ float sPar[8 * R_ * DIM_];// 8-way partials (32KB); reused L3
    __shared__ float sVal[32];
    __shared__ int   sIdxW[32];

    // Prefetch q rows (hidden under phase-1 ALU).
    if (t < 256)
        ((float4*)sQ)[t] = ((const float4*)(q + (size_t)bq0 * DIM_))[t];

    // -------- Phase 1: Gumbel-argmax; row r = w>>2, sub-range sub = w&3 -----
    // Thread handles 4 CONSECUTIVE candidates -> one float4 logits load.
    {
        const int r = w >> 2, sub = w & 3;
        const int bq = bq0 + r;
        const float4 lv = ((const float4*)(att_logits + (size_t)bq * CL_))
                              [sub * 32 + ln];
        const float lvs[4] = {lv.x, lv.y, lv.z, lv.w};
        const int c0 = sub * 128 + ln * 4;
        const float TINY = 1.17549435e-38f;
        float best = -__int_as_float(0x7f800000);
        int bi = 0;
#pragma unroll
        for (int i = 0; i < 4; ++i) {
            const int c = c0 + i;
            uint32_t j = (uint32_t)bq * (uint32_t)CL_ + (uint32_t)c;
            float u = bits_to_unit(jax_bits(kc0, kc1, j));
            u = fmaxf(TINY, u * (1.0f - TINY) + TINY);
            // g = -log(-log(u)) = -ln2*log2(-log2(u)) - ln(ln2)
            float lg1; asm("lg2.approx.f32 %0, %1;" : "=f"(lg1) : "f"(u));
            float L = -lg1;
            float lg2v; asm("lg2.approx.f32 %0, %1;" : "=f"(lg2v) : "f"(L));
            float g = fmaf(-0.693147180559945f, lg2v, 0.366512920581664f);
            float v = g + lvs[i];
            if (v > best || (v == best && c < bi)) { best = v; bi = c; }
        }
#pragma unroll
        for (int off = 16; off; off >>= 1) {
            float v2 = __shfl_xor_sync(0xffffffffu, best, off);
            int   i2 = __shfl_xor_sync(0xffffffffu, bi,   off);
            if (v2 > best || (v2 == best && i2 < bi)) { best = v2; bi = i2; }
        }
        if (ln == 0) { sVal[w] = best; sIdxW[w] = bi; }
    }

    // Precompute eps for the sample stage (held in a register until the end).
    float epsv = 0.f;
    if (t < R_ * YD_) {                  // 128 threads
        uint32_t m = (uint32_t)(bq0 + (t >> 4)) * (uint32_t)YD_ + (uint32_t)(t & 15);
        float u = bits_to_unit(jax_bits(ke0, ke1, m));
        const float lo = -0.99999994f;
        float x = fmaxf(lo, u * (1.0f - lo) + lo);
        epsv = 1.41421356237f * erfinv_xla(x);
    }
    __syncthreads();                     // A: sVal/sIdxW + sQ visible

    // Warps 0-7 finalize their row's argmax and issue the f-row gather; its
    // LDG latency hides under the layer-1 q-part below.
    float4 fgv;
    const bool gat = (t < 256);
    if (gat) {
        const int r = w;                 // 0..7
        float bv = sVal[r * 4]; int bj = sIdxW[r * 4];
#pragma unroll
        for (int k = 1; k < 4; ++k) {
            float v2 = sVal[r * 4 + k]; int i2 = sIdxW[r * 4 + k];
            if (v2 > bv || (v2 == bv && i2 < bj)) { bv = v2; bj = i2; }
        }
        fgv = ((const float4*)(f_embed + ((size_t)b * CL_ + bj) * DIM_))[ln];
    }

    const int c   = t & 127;             // output column
    const int oct = t >> 7;              // d-octant 0..7 (16 d's each)
    float acc[R_];
#pragma unroll
    for (int r = 0; r < R_; ++r) acc[r] = 0.f;

    // -------- Layer 1, q-part: acc += q@W1q ---------------------------------
    {
        const float* wq = W1q + c;
#pragma unroll
        for (int i = 0; i < 4; ++i) {
            const int d = oct * 16 + i * 4;
            float w0 = wq[(d + 0) * DIM_], w1 = wq[(d + 1) * DIM_];
            float w2v = wq[(d + 2) * DIM_], w3 = wq[(d + 3) * DIM_];
#pragma unroll
            for (int r = 0; r < R_; ++r) {
                float4 qv = ((const float4*)sQ)[r * 32 + (d >> 2)];
                acc[r] = fmaf(qv.x, w0, acc[r]); acc[r] = fmaf(qv.y, w1, acc[r]);
                acc[r] = fmaf(qv.z, w2v, acc[r]); acc[r] = fmaf(qv.w, w3, acc[r]);
            }
        }
    }
    if (gat) ((float4*)(sF + w * DIM_))[ln] = fgv;
    __syncthreads();                     // B: sF visible

    // -------- Layer 1, f-part: acc += f@W1f; store partials -----------------
    {
        const float* wf = W1f + c;
#pragma unroll
        for (int i = 0; i < 4; ++i) {
            const int d = oct * 16 + i * 4;
            float w0 = wf[(d + 0) * DIM_], w1 = wf[(d + 1) * DIM_];
            float w2v = wf[(d + 2) * DIM_], w3 = wf[(d + 3) * DIM_];
#pragma unroll
            for (int r = 0; r < R_; ++r) {
                float4 fv = ((const float4*)sF)[r * 32 + (d >> 2)];
                acc[r] = fmaf(fv.x, w0, acc[r]); acc[r] = fmaf(fv.y, w1, acc[r]);
                acc[r] = fmaf(fv.z, w2v, acc[r]); acc[r] = fmaf(fv.w, w3, acc[r]);
            }
        }
#pragma unroll
        for (int r = 0; r < R_; ++r) sPar[oct * 1024 + r * DIM_ + c] = acc[r];
    }
    __syncthreads();                     // C
    {
        float s = 0.f;
#pragma unroll
        for (int k = 0; k < 8; ++k) s += sPar[k * 1024 + t];
        sH[t] = fmaxf(s + b1[c], 0.f);
    }
    __syncthreads();                     // D

    // -------- Layer 2: h2 = relu(h@W2 + b2) ---------------------------------
    {
#pragma unroll
        for (int r = 0; r < R_; ++r) acc[r] = 0.f;
        const float* w2 = W2 + c;
#pragma unroll
        for (int i = 0; i < 4; ++i) {
            const int d = oct * 16 + i * 4;
            float w0 = w2[(d + 0) * DIM_], w1 = w2[(d + 1) * DIM_];
            float w2v = w2[(d + 2) * DIM_], w3 = w2[(d + 3) * DIM_];
#pragma unroll
            for (int r = 0; r < R_; ++r) {
                float4 hv = ((const float4*)sH)[r * 32 + (d >> 2)];
                acc[r] = fmaf(hv.x, w0, acc[r]); acc[r] = fmaf(hv.y, w1, acc[r]);
                acc[r] = fmaf(hv.z, w2v, acc[r]); acc[r] = fmaf(hv.w, w3, acc[r]);
            }
        }
#pragma unroll
        for (int r = 0; r < R_; ++r) sPar[oct * 1024 + r * DIM_ + c] = acc[r];
    }
    __syncthreads();                     // E
    {
        float s = 0.f;
#pragma unroll
        for (int k = 0; k < 8; ++k) s += sPar[k * 1024 + t];
        sQ[t] = fmaxf(s + b2[c], 0.f);   // sQ := h2
    }
    __syncthreads();                     // F

    // -------- Layer 3: thread = (o=ln, g=w&15, rowhalf=w>>4) ----------------
    // 8 weight LDGs reused across 4 rows (2x total redundancy vs 8x before).
    {
        const int o  = ln;               // output column 0..31
        const int g  = w & 15;           // d-group (8 d's)
        const int rh = w >> 4;           // row half: rows [rh*4, rh*4+4)
        const float* wp = Wout + g * 8 * 32 + o;
        float wv0 = wp[0 * 32], wv1 = wp[1 * 32], wv2 = wp[2 * 32], wv3 = wp[3 * 32];
        float wv4 = wp[4 * 32], wv5 = wp[5 * 32], wv6 = wp[6 * 32], wv7 = wp[7 * 32];
#pragma unroll
        for (int k = 0; k < 4; ++k) {
            const int r = rh * 4 + k;
            float4 h0 = ((const float4*)sQ)[r * 32 + g * 2];
            float4 h1 = ((const float4*)sQ)[r * 32 + g * 2 + 1];
            float a0 = fmaf(h0.x, wv0, fmaf(h0.y, wv1, 0.f));
            float a1 = fmaf(h0.z, wv2, fmaf(h0.w, wv3, 0.f));
            float a2 = fmaf(h1.x, wv4, fmaf(h1.y, wv5, 0.f));
            float a3 = fmaf(h1.z, wv6, fmaf(h1.w, wv7, 0.f));
            sPar[g * 256 + r * 32 + o] = (a0 + a1) + (a2 + a3);
        }
    }
    __syncthreads();                     // G

    // -------- Tail: reduce mu/s + sample (eps precomputed) ------------------
    if (t < R_ * YD_) {                  // 128 threads
        const int rr = t >> 4, y = t & 15;
        float mu = bout[y];
        float sv = bout[YD_ + y];
#pragma unroll
        for (int g = 0; g < 16; ++g) {
            mu += sPar[g * 256 + rr * 32 + y];
            sv += sPar[g * 256 + rr * 32 + YD_ + y];
        }
        float s = fmaxf(-15.0f, sv);
        float sigma = fmaxf(s, 0.0f) + log1pf(expf(-fabsf(s)));
        out[(size_t)bq0 * YD_ + t] = fmaf(sigma, epsv, mu);
    }
}

// ---------------------------------------------------------------------- launch
extern "C" void kernel_launch(void* const* d_in, const int* in_sizes, int n_in,
                              void* d_out, int out_size) {
    const float* q     = (const float*)d_in[0];
    const float* f_emb = (const float*)d_in[1];
    const float* alog  = (const float*)d_in[2];
    const float* W1q   = (const float*)d_in[3];
    const float* W1f   = (const float*)d_in[4];
    const float* b1    = (const float*)d_in[5];
    const float* W2    = (const float*)d_in[6];
    const float* b2    = (const float*)d_in[7];
    const float* Wout  = (const float*)d_in[8];
    const float* bout  = (const float*)d_in[9];
    float* out = (float*)d_out;

    // split(jax.random.key(1), 2), partitionable: subkey_i = tf(key, (0, i))
    uint32_t kc0, kc1, ke0, ke1;
    tf2x32(0u, 1u, 0u, 0u, kc0, kc1);
    tf2x32(0u, 1u, 0u, 1u, ke0, ke1);

    pp_fused_kernel<<<(B_ * QL_) / R_, 1024>>>(q, f_emb, alog, W1q, W1f, b1,
                                               W2, b2, Wout, bout, out,
                                               kc0, kc1, ke0, ke1);
}

// round 12
// speedup vs baseline: 2.2478x; 2.2478x over previous
#include <cuda_runtime.h>
#include <stdint.h>

// ProbabilisticPrediction fused kernel, R12 = exact R6 (best: 14.8us) + one
// stall fix: first-iteration W2 / Wout weight loads hoisted across the
// preceding barriers so their L2 latency hides under the smem reductions.
// 8 rows/block, 1024 threads, grid 128, 8-way d-split, pipelined weight
// loads, MUFU lg2 Gumbel, f-gather hidden under layer-1 q-part.
// Gumbel-argmax (JAX threefry partitionable) selects one mixture component
// per (b,q); the 3-layer MLP is evaluated only at those 1024 points.

#define B_   4
#define QL_  256
#define CL_  512
#define DIM_ 128
#define YD_  16
#define R_   8

// ---------------------------------------------------------------- threefry2x32
__host__ __device__ inline void tf2x32(uint32_t k0, uint32_t k1,
                                       uint32_t c0, uint32_t c1,
                                       uint32_t& o0, uint32_t& o1) {
    uint32_t k2 = k0 ^ k1 ^ 0x1BD11BDAu;
    uint32_t x0 = c0 + k0, x1 = c1 + k1;
#define TFR(d) do { x0 += x1; x1 = (x1 << (d)) | (x1 >> (32 - (d))); x1 ^= x0; } while (0)
    TFR(13); TFR(15); TFR(26); TFR(6);   x0 += k1; x1 += k2 + 1u;
    TFR(17); TFR(29); TFR(16); TFR(24);  x0 += k2; x1 += k0 + 2u;
    TFR(13); TFR(15); TFR(26); TFR(6);   x0 += k0; x1 += k1 + 3u;
    TFR(17); TFR(29); TFR(16); TFR(24);  x0 += k1; x1 += k2 + 4u;
    TFR(13); TFR(15); TFR(26); TFR(6);   x0 += k2; x1 += k0 + 5u;
#undef TFR
    o0 = x0; o1 = x1;
}

__device__ inline uint32_t jax_bits(uint32_t k0, uint32_t k1, uint32_t j) {
    uint32_t o0, o1;
    tf2x32(k0, k1, 0u, j, o0, o1);   // partitionable: 64-bit iota (0, j)
    return o0 ^ o1;
}

__device__ inline float bits_to_unit(uint32_t b) {      // [0, 1)
    return __uint_as_float((b >> 9) | 0x3f800000u) - 1.0f;
}

// XLA ErfInv32 (Giles) -- matches jax.random.normal exactly.
__device__ inline float erfinv_xla(float x) {
    float w = -log1pf(-x * x);
    float p;
    if (w < 5.0f) {
        w -= 2.5f;
        p =            2.81022636e-08f;
        p = fmaf(p, w, 3.43273939e-07f);
        p = fmaf(p, w, -3.5233877e-06f);
        p = fmaf(p, w, -4.39150654e-06f);
        p = fmaf(p, w, 0.00021858087f);
        p = fmaf(p, w, -0.00125372503f);
        p = fmaf(p, w, -0.00417768164f);
        p = fmaf(p, w, 0.246640727f);
        p = fmaf(p, w, 1.50140941f);
    } else {
        w = sqrtf(w) - 3.0f;
        p =            -0.000200214257f;
        p = fmaf(p, w, 0.000100950558f);
        p = fmaf(p, w, 0.00134934322f);
        p = fmaf(p, w, -0.00367342844f);
        p = fmaf(p, w, 0.00573950773f);
        p = fmaf(p, w, -0.0076224613f);
        p = fmaf(p, w, 0.00943887047f);
        p = fmaf(p, w, 1.00167406f);
        p = fmaf(p, w, 2.83297682f);
    }
    return p * x;
}

// ---------------------------------------------------------------------- kernel
__global__ __launch_bounds__(1024, 1)
void pp_fused_kernel(const float* __restrict__ q,
                     const float* __restrict__ f_embed,
                     const float* __restrict__ att_logits,
                     const float* __restrict__ W1q,
                     const float* __restrict__ W1f,
                     const float* __restrict__ b1,
                     const float* __restrict__ W2,
                     const float* __restrict__ b2,
                     const float* __restrict__ Wout,
                     const float* __restrict__ bout,
                     float* __restrict__ out,
                     uint32_t kc0, uint32_t kc1,
                     uint32_t ke0, uint32_t ke1)
{
    const int t   = threadIdx.x;         // 0..1023
    const int w   = t >> 5;              // warp 0..31
    const int ln  = t & 31;
    const int bq0 = blockIdx.x * R_;
    const int b   = bq0 >> 8;            // all R_ rows share b (8 | 256)

    __shared__ float sQ[R_ * DIM_];      // q rows; later h2
    __shared__ float sF[R_ * DIM_];      // selected f rows
    __shared__ float sH[R_ * DIM_];      // h1
    __shared__ float sPar[8 * R_ * DIM_];// 8-way partials (32KB); reused L3
    __shared__ float sO[R_ * 2 * YD_];
    __shared__ float sVal[32];
    __shared__ int   sIdxW[32];

    // Prefetch q rows (hidden under phase-1 ALU).
    if (t < 256)
        ((float4*)sQ)[t] = ((const float4*)(q + (size_t)bq0 * DIM_))[t];

    // -------- Phase 1: Gumbel-argmax; row r = w>>2, sub-range sub = w&3 -----
    {
        const int r = w >> 2, sub = w & 3;
        const int bq = bq0 + r;
        const float* lrow = att_logits + (size_t)bq * CL_;
        const float TINY = 1.17549435e-38f;
        float best = -__int_as_float(0x7f800000);
        int bi = 0;
#pragma unroll
        for (int i = 0; i < 4; ++i) {
            int c = sub * 128 + i * 32 + ln;
            uint32_t j = (uint32_t)bq * (uint32_t)CL_ + (uint32_t)c;
            float u = bits_to_unit(jax_bits(kc0, kc1, j));
            u = fmaxf(TINY, u * (1.0f - TINY) + TINY);
            // g = -log(-log(u)) = -ln2*log2(-log2(u)) - ln(ln2)
            float lg1; asm("lg2.approx.f32 %0, %1;" : "=f"(lg1) : "f"(u));
            float L = -lg1;
            float lg2v; asm("lg2.approx.f32 %0, %1;" : "=f"(lg2v) : "f"(L));
            float g = fmaf(-0.693147180559945f, lg2v, 0.366512920581664f);
            float v = g + lrow[c];
            if (v > best || (v == best && c < bi)) { best = v; bi = c; }
        }
#pragma unroll
        for (int off = 16; off; off >>= 1) {
            float v2 = __shfl_xor_sync(0xffffffffu, best, off);
            int   i2 = __shfl_xor_sync(0xffffffffu, bi,   off);
            if (v2 > best || (v2 == best && i2 < bi)) { best = v2; bi = i2; }
        }
        if (ln == 0) { sVal[w] = best; sIdxW[w] = bi; }
    }

    // Precompute eps for the sample stage (held in a register until the end).
    float epsv = 0.f;
    if (t < R_ * YD_) {                  // 128 threads
        uint32_t m = (uint32_t)(bq0 + (t >> 4)) * (uint32_t)YD_ + (uint32_t)(t & 15);
        float u = bits_to_unit(jax_bits(ke0, ke1, m));
        const float lo = -0.99999994f;
        float x = fmaxf(lo, u * (1.0f - lo) + lo);
        epsv = 1.41421356237f * erfinv_xla(x);
    }
    __syncthreads();                     // A: sVal/sIdxW + sQ visible

    // Warps 0-7 finalize their row's argmax and start the f-row gather; the
    // gather's LDG latency hides under the layer-1 q-part below.
    float4 fgv;
    const bool gat = (t < 256);
    if (gat) {
        const int r = w;                 // 0..7
        float bv = sVal[r * 4]; int bj = sIdxW[r * 4];
#pragma unroll
        for (int k = 1; k < 4; ++k) {
            float v2 = sVal[r * 4 + k]; int i2 = sIdxW[r * 4 + k];
            if (v2 > bv || (v2 == bv && i2 < bj)) { bv = v2; bj = i2; }
        }
        fgv = ((const float4*)(f_embed + ((size_t)b * CL_ + bj) * DIM_))[ln];
    }

    const int c   = t & 127;             // output column
    const int oct = t >> 7;              // d-octant 0..7 (16 d's each)

    // -------- Layer 1, q-part: acc += q@W1q (pipelined weight loads) --------
    float acc[R_];
#pragma unroll
    for (int r = 0; r < R_; ++r) acc[r] = 0.f;
    {
        const float* wq = W1q + c;
        float c0, c1, c2, c3;
        {
            const int d = oct * 16;
            c0 = wq[(d + 0) * DIM_]; c1 = wq[(d + 1) * DIM_];
            c2 = wq[(d + 2) * DIM_]; c3 = wq[(d + 3) * DIM_];
        }
#pragma unroll
        for (int i = 0; i < 4; ++i) {
            float n0, n1, n2, n3;
            if (i < 3) {                // prefetch next iteration's weights
                const int dn = oct * 16 + (i + 1) * 4;
                n0 = wq[(dn + 0) * DIM_]; n1 = wq[(dn + 1) * DIM_];
                n2 = wq[(dn + 2) * DIM_]; n3 = wq[(dn + 3) * DIM_];
            }
            const int d = oct * 16 + i * 4;
#pragma unroll
            for (int r = 0; r < R_; ++r) {
                float4 qv = ((const float4*)sQ)[r * 32 + (d >> 2)];
                acc[r] = fmaf(qv.x, c0, acc[r]); acc[r] = fmaf(qv.y, c1, acc[r]);
                acc[r] = fmaf(qv.z, c2, acc[r]); acc[r] = fmaf(qv.w, c3, acc[r]);
            }
            if (i < 3) { c0 = n0; c1 = n1; c2 = n2; c3 = n3; }
        }
    }
    if (gat) ((float4*)(sF + w * DIM_))[ln] = fgv;
    __syncthreads();                     // B: sF visible

    // -------- Layer 1, f-part: acc += f@W1f; store partials -----------------
    {
        const float* wf = W1f + c;
        float c0, c1, c2, c3;
        {
            const int d = oct * 16;
            c0 = wf[(d + 0) * DIM_]; c1 = wf[(d + 1) * DIM_];
            c2 = wf[(d + 2) * DIM_]; c3 = wf[(d + 3) * DIM_];
        }
#pragma unroll
        for (int i = 0; i < 4; ++i) {
            float n0, n1, n2, n3;
            if (i < 3) {
                const int dn = oct * 16 + (i + 1) * 4;
                n0 = wf[(dn + 0) * DIM_]; n1 = wf[(dn + 1) * DIM_];
                n2 = wf[(dn + 2) * DIM_]; n3 = wf[(dn + 3) * DIM_];
            }
            const int d = oct * 16 + i * 4;
#pragma unroll
            for (int r = 0; r < R_; ++r) {
                float4 fv = ((const float4*)sF)[r * 32 + (d >> 2)];
                acc[r] = fmaf(fv.x, c0, acc[r]); acc[r] = fmaf(fv.y, c1, acc[r]);
                acc[r] = fmaf(fv.z, c2, acc[r]); acc[r] = fmaf(fv.w, c3, acc[r]);
            }
            if (i < 3) { c0 = n0; c1 = n1; c2 = n2; c3 = n3; }
        }
#pragma unroll
        for (int r = 0; r < R_; ++r) sPar[oct * 1024 + r * DIM_ + c] = acc[r];
    }

    // R12 edit 1: issue layer-2's first weight loads BEFORE barrier C so the
    // L2 latency hides under the barrier + layer-1 reduction.
    const float* w2p = W2 + c;
    float p20, p21, p22, p23;
    {
        const int d = oct * 16;
        p20 = w2p[(d + 0) * DIM_]; p21 = w2p[(d + 1) * DIM_];
        p22 = w2p[(d + 2) * DIM_]; p23 = w2p[(d + 3) * DIM_];
    }
    __syncthreads();                     // C
    {
        float s = 0.f;
#pragma unroll
        for (int k = 0; k < 8; ++k) s += sPar[k * 1024 + t];
        sH[t] = fmaxf(s + b1[c], 0.f);
    }
    __syncthreads();                     // D

    // -------- Layer 2: h2 = relu(h@W2 + b2), pipelined loads ----------------
    {
#pragma unroll
        for (int r = 0; r < R_; ++r) acc[r] = 0.f;
        float c0 = p20, c1 = p21, c2 = p22, c3 = p23;
#pragma unroll
        for (int i = 0; i < 4; ++i) {
            float n0, n1, n2, n3;
            if (i < 3) {
                const int dn = oct * 16 + (i + 1) * 4;
                n0 = w2p[(dn + 0) * DIM_]; n1 = w2p[(dn + 1) * DIM_];
                n2 = w2p[(dn + 2) * DIM_]; n3 = w2p[(dn + 3) * DIM_];
            }
            const int d = oct * 16 + i * 4;
#pragma unroll
            for (int r = 0; r < R_; ++r) {
                float4 hv = ((const float4*)sH)[r * 32 + (d >> 2)];
                acc[r] = fmaf(hv.x, c0, acc[r]); acc[r] = fmaf(hv.y, c1, acc[r]);
                acc[r] = fmaf(hv.z, c2, acc[r]); acc[r] = fmaf(hv.w, c3, acc[r]);
            }
            if (i < 3) { c0 = n0; c1 = n1; c2 = n2; c3 = n3; }
        }
#pragma unroll
        for (int r = 0; r < R_; ++r) sPar[oct * 1024 + r * DIM_ + c] = acc[r];
    }

    // R12 edit 2: issue layer-3's first Wout loads BEFORE barrier E/F.
    const int p3  = t >> 8;              // 0..3, d in [p3*32, p3*32+32)
    const int rr3 = (t >> 5) & 7;
    float pw0, pw1, pw2, pw3;
    {
        const int d = p3 * 32;
        pw0 = Wout[(d + 0) * 32 + ln]; pw1 = Wout[(d + 1) * 32 + ln];
        pw2 = Wout[(d + 2) * 32 + ln]; pw3 = Wout[(d + 3) * 32 + ln];
    }
    __syncthreads();                     // E
    {
        float s = 0.f;
#pragma unroll
        for (int k = 0; k < 8; ++k) s += sPar[k * 1024 + t];
        sQ[t] = fmaxf(s + b2[c], 0.f);   // sQ := h2
    }
    __syncthreads();                     // F

    // -------- Layer 3: out = h2@Wout + bout  (4-way d-split) ----------------
    {
        const int o = ln;
        float a0 = 0.f, a1 = 0.f;
        {   // first d4 uses the prefetched weights
            const int d = p3 * 32;
            float4 hv = ((const float4*)sQ)[rr3 * 32 + (d >> 2)];
            a0 = fmaf(hv.x, pw0, a0);
            a1 = fmaf(hv.y, pw1, a1);
            a0 = fmaf(hv.z, pw2, a0);
            a1 = fmaf(hv.w, pw3, a1);
        }
#pragma unroll
        for (int d4 = 1; d4 < 8; ++d4) {
            const int d = p3 * 32 + d4 * 4;
            float4 hv = ((const float4*)sQ)[rr3 * 32 + (d >> 2)];
            a0 = fmaf(hv.x, Wout[(d + 0) * 32 + o], a0);
            a1 = fmaf(hv.y, Wout[(d + 1) * 32 + o], a1);
            a0 = fmaf(hv.z, Wout[(d + 2) * 32 + o], a0);
            a1 = fmaf(hv.w, Wout[(d + 3) * 32 + o], a1);
        }
        sPar[p3 * 256 + rr3 * 32 + o] = a0 + a1;
    }
    __syncthreads();                     // G
    if (t < 256) {
        sO[t] = sPar[t] + sPar[256 + t] + sPar[512 + t] + sPar[768 + t]
              + bout[t & 31];
    }
    __syncthreads();                     // H

    // -------- Sample: y = mu + softplus(max(-15,s)) * eps -------------------
    if (t < R_ * YD_) {                  // 128 threads
        const int rr = t >> 4, y = t & 15;
        float s = fmaxf(-15.0f, sO[rr * 32 + YD_ + y]);
        float sigma = fmaxf(s, 0.0f) + log1pf(expf(-fabsf(s)));
        out[(size_t)bq0 * YD_ + t] = fmaf(sigma, epsv, sO[rr * 32 + y]);
    }
}

// ---------------------------------------------------------------------- launch
extern "C" void kernel_launch(void* const* d_in, const int* in_sizes, int n_in,
                              void* d_out, int out_size) {
    const float* q     = (const float*)d_in[0];
    const float* f_emb = (const float*)d_in[1];
    const float* alog  = (const float*)d_in[2];
    const float* W1q   = (const float*)d_in[3];
    const float* W1f   = (const float*)d_in[4];
    const float* b1    = (const float*)d_in[5];
    const float* W2    = (const float*)d_in[6];
    const float* b2    = (const float*)d_in[7];
    const float* Wout  = (const float*)d_in[8];
    const float* bout  = (const float*)d_in[9];
    float* out = (float*)d_out;

    // split(jax.random.key(1), 2), partitionable: subkey_i = tf(key, (0, i))
    uint32_t kc0, kc1, ke0, ke1;
    tf2x32(0u, 1u, 0u, 0u, kc0, kc1);
    tf2x32(0u, 1u, 0u, 1u, ke0, ke1);

    pp_fused_kernel<<<(B_ * QL_) / R_, 1024>>>(q, f_emb, alog, W1q, W1f, b1,
                                               W2, b2, Wout, bout, out,
                                               kc0, kc1, ke0, ke1);
}